// round 3
// baseline (speedup 1.0000x reference)
#include <cuda_runtime.h>
#include <float.h>

#define NTOK 4096
#define DEMB 1024
#define NH   8
#define DH   128
#define CWW  256
#define QK_SCALE 0.08838834764831845f  // 1/sqrt(128)

// ---------------- scratch (static device memory; no allocations) ------------
__device__ float4 g_q4[NTOK * DH / 4];
__device__ float4 g_k4[NTOK * DH / 4];
__device__ float4 g_v4[NTOK * DH / 4];
__device__ float4 g_av4[NTOK * DH / 4];
__device__ float4 g_delta4[NTOK * DEMB / 4];

// ---------------- SGEMM: C[n][m] = sum_k A[n][k] * B[m][k] ------------------
// A: [N x K] row-major, B: [M x K] row-major ("NT" GEMM).
// Block tile 128(n) x 64(m), K-tile 16, 256 threads, 8x4 accum per thread.
template <int K, int M>
__device__ __forceinline__ void gemm_body(const float* __restrict__ A,
                                          const float* __restrict__ B,
                                          float* __restrict__ C) {
    __shared__ float As[16][132];  // padded: STS conflict reduction, 16B-aligned rows
    __shared__ float Bs[16][68];
    const int tid = threadIdx.x;
    const int tx = tid & 15;   // 4 output cols each
    const int ty = tid >> 4;   // 8 output rows each
    const int n0 = blockIdx.y * 128;
    const int m0 = blockIdx.x * 64;
    const float* Ag = A + (size_t)n0 * K;
    const float* Bg = B + (size_t)m0 * K;

    float acc[8][4];
#pragma unroll
    for (int i = 0; i < 8; i++)
#pragma unroll
        for (int j = 0; j < 4; j++) acc[i][j] = 0.f;

    for (int k0 = 0; k0 < K; k0 += 16) {
        // stage A tile (128 rows x 16 k) : 512 float4, 2 per thread
#pragma unroll
        for (int i = 0; i < 2; i++) {
            int idx = tid + 256 * i;           // 0..511
            int row = idx >> 2;                // 0..127
            int kq  = (idx & 3) << 2;          // 0,4,8,12
            float4 v = *(const float4*)(Ag + (size_t)row * K + k0 + kq);
            As[kq + 0][row] = v.x;
            As[kq + 1][row] = v.y;
            As[kq + 2][row] = v.z;
            As[kq + 3][row] = v.w;
        }
        // stage B tile (64 rows x 16 k) : 256 float4, 1 per thread
        {
            int row = tid >> 2;                // 0..63
            int kq  = (tid & 3) << 2;
            float4 v = *(const float4*)(Bg + (size_t)row * K + k0 + kq);
            Bs[kq + 0][row] = v.x;
            Bs[kq + 1][row] = v.y;
            Bs[kq + 2][row] = v.z;
            Bs[kq + 3][row] = v.w;
        }
        __syncthreads();
#pragma unroll
        for (int kk = 0; kk < 16; kk++) {
            float4 a0 = *(const float4*)&As[kk][ty * 8];
            float4 a1 = *(const float4*)&As[kk][ty * 8 + 4];
            float4 bv = *(const float4*)&Bs[kk][tx * 4];
            float a[8] = {a0.x, a0.y, a0.z, a0.w, a1.x, a1.y, a1.z, a1.w};
            float b[4] = {bv.x, bv.y, bv.z, bv.w};
#pragma unroll
            for (int i = 0; i < 8; i++)
#pragma unroll
                for (int j = 0; j < 4; j++) acc[i][j] += a[i] * b[j];
        }
        __syncthreads();
    }
#pragma unroll
    for (int i = 0; i < 8; i++) {
        float4 v = make_float4(acc[i][0], acc[i][1], acc[i][2], acc[i][3]);
        *(float4*)(C + (size_t)(n0 + ty * 8 + i) * M + m0 + tx * 4) = v;
    }
}

// QKV projections, batched over blockIdx.z (0:q 1:k 2:vd). K=1024, M=128.
__global__ void __launch_bounds__(256) k_gemm_qkv(const float* __restrict__ e,
                                                  const float* __restrict__ Wq,
                                                  const float* __restrict__ Wk,
                                                  const float* __restrict__ Wvd) {
    const float* B = (blockIdx.z == 0) ? Wq : (blockIdx.z == 1 ? Wk : Wvd);
    float* C = (blockIdx.z == 0) ? (float*)g_q4
                                 : (blockIdx.z == 1 ? (float*)g_k4 : (float*)g_v4);
    gemm_body<1024, 128>(e, B, C);
}

// out projection: delta = av @ Wvu[h]^T. K=128, M=1024.
__global__ void __launch_bounds__(256) k_gemm_out(const float* __restrict__ Wvu) {
    gemm_body<128, 1024>((const float*)g_av4, Wvu, (float*)g_delta4);
}

// ---------------- banded attention (online softmax) -------------------------
// 256 threads (8 warps), 32 queries/block (4 per warp). Key chunks of 32.
// K tile transposed + XOR-swizzled, V tile row-major. Lane owns key=lane for
// scores and dh-quad=lane for output.
__global__ void __launch_bounds__(256) k_attn() {
    __shared__ float4 Qs[32 * 32];  // [q][d4]
    __shared__ float4 Kt[32 * 32];  // [d4][key ^ d4]
    __shared__ float4 Vs[32 * 32];  // [key][d4]
    const int tid  = threadIdx.x;
    const int lane = tid & 31;
    const int w    = tid >> 5;
    const int q0   = blockIdx.x * 32;

#pragma unroll
    for (int i = 0; i < 4; i++)
        Qs[tid + 256 * i] = g_q4[q0 * 32 + tid + 256 * i];

    float m[4], l[4];
    float4 o[4];
#pragma unroll
    for (int qi = 0; qi < 4; qi++) {
        m[qi] = -FLT_MAX;
        l[qi] = 0.f;
        o[qi] = make_float4(0.f, 0.f, 0.f, 0.f);
    }
    const int jbase = q0 + 4 * w;
    const int lo = (q0 >= CWW) ? (q0 - CWW) : 0;
    const int hi = min(q0 + 31 + CWW, NTOK);  // exclusive key bound

    for (int kc = lo; kc < hi; kc += 32) {
        __syncthreads();
#pragma unroll
        for (int i = 0; i < 4; i++) {
            int idx = tid + 256 * i;   // 0..1023
            int key = idx >> 5;        // 0..31
            int d4  = idx & 31;        // == lane
            int kg  = kc + key;
            float4 kv = make_float4(0.f, 0.f, 0.f, 0.f);
            float4 vv = make_float4(0.f, 0.f, 0.f, 0.f);
            if (kg < NTOK) {
                kv = g_k4[kg * 32 + d4];
                vv = g_v4[kg * 32 + d4];
            }
            Kt[(d4 << 5) + (key ^ d4)] = kv;
            Vs[(key << 5) + d4] = vv;
        }
        __syncthreads();

        // scores for key = kc + lane
        float s[4] = {0.f, 0.f, 0.f, 0.f};
#pragma unroll 8
        for (int d4 = 0; d4 < 32; d4++) {
            float4 kv = Kt[(d4 << 5) + (lane ^ d4)];
#pragma unroll
            for (int qi = 0; qi < 4; qi++) {
                float4 qv = Qs[(4 * w + qi) * 32 + d4];  // broadcast
                s[qi] += qv.x * kv.x + qv.y * kv.y + qv.z * kv.z + qv.w * kv.w;
            }
        }

        const int kg = kc + lane;
        float p[4];
#pragma unroll
        for (int qi = 0; qi < 4; qi++) {
            int j = jbase + qi;
            float sv = s[qi] * QK_SCALE;
            bool ok = (kg >= j - CWW) && (kg < j + CWW) && (kg < NTOK);
            sv = ok ? sv : -FLT_MAX;
            float c = sv;
#pragma unroll
            for (int off = 16; off; off >>= 1)
                c = fmaxf(c, __shfl_xor_sync(0xffffffffu, c, off));
            float mn   = fmaxf(m[qi], c);
            float corr = __expf(m[qi] - mn);
            float pv   = __expf(sv - mn);
            float su = pv;
#pragma unroll
            for (int off = 16; off; off >>= 1)
                su += __shfl_xor_sync(0xffffffffu, su, off);
            l[qi] = l[qi] * corr + su;
            m[qi] = mn;
            o[qi].x *= corr; o[qi].y *= corr; o[qi].z *= corr; o[qi].w *= corr;
            p[qi] = pv;
        }

        // P @ V : lane owns dh dims [4*lane, 4*lane+4)
#pragma unroll 4
        for (int k = 0; k < 32; k++) {
            float4 v = Vs[(k << 5) + lane];
#pragma unroll
            for (int qi = 0; qi < 4; qi++) {
                float wq = __shfl_sync(0xffffffffu, p[qi], k);
                o[qi].x += wq * v.x;
                o[qi].y += wq * v.y;
                o[qi].z += wq * v.z;
                o[qi].w += wq * v.w;
            }
        }
    }

#pragma unroll
    for (int qi = 0; qi < 4; qi++) {
        float r = 1.f / l[qi];
        g_av4[(jbase + qi) * 32 + lane] =
            make_float4(o[qi].x * r, o[qi].y * r, o[qi].z * r, o[qi].w * r);
    }
}

// ---------------- residual + norm, accumulate into e ------------------------
__device__ __forceinline__ float block_sum(float v, float* red) {
#pragma unroll
    for (int off = 16; off; off >>= 1) v += __shfl_xor_sync(0xffffffffu, v, off);
    if ((threadIdx.x & 31) == 0) red[threadIdx.x >> 5] = v;
    __syncthreads();
    float s = ((red[0] + red[1]) + (red[2] + red[3])) +
              ((red[4] + red[5]) + (red[6] + red[7]));
    __syncthreads();
    return s;
}

__global__ void __launch_bounds__(256) k_norm(float* __restrict__ e) {
    __shared__ float red[8];
    const int r = blockIdx.x;
    const int tid = threadIdx.x;
    const float* dl = (const float*)g_delta4;
    float ev[4], o[4];
    float s1 = 0.f;
#pragma unroll
    for (int i = 0; i < 4; i++) {
        int idx = r * DEMB + tid + 256 * i;
        ev[i] = e[idx];
        o[i]  = ev[i] + dl[idx];
        s1 += o[i];
    }
    s1 = block_sum(s1, red);
    float inv_mean1 = (float)DEMB / s1;           // out /= mean(out)
    float s2 = 0.f;
#pragma unroll
    for (int i = 0; i < 4; i++) {
        o[i] *= inv_mean1;
        s2 += o[i];
    }
    s2 = block_sum(s2, red);
    float mu = s2 * (1.0f / DEMB);
    float sq = 0.f;
#pragma unroll
    for (int i = 0; i < 4; i++) {
        float d = o[i] - mu;
        sq += d * d;
    }
    sq = block_sum(sq, red);
    float inv_sd = rsqrtf(sq * (1.0f / (DEMB - 1)));  // ddof=1
#pragma unroll
    for (int i = 0; i < 4; i++) {
        int idx = r * DEMB + tid + 256 * i;
        e[idx] = ev[i] + (o[i] - mu) * inv_sd + mu;
    }
}

// ---------------- copy & final scale ----------------------------------------
__global__ void __launch_bounds__(256) k_copy(float4* __restrict__ dst,
                                              const float4* __restrict__ src) {
    int i = blockIdx.x * 256 + threadIdx.x;
    dst[i] = src[i];
}

__global__ void __launch_bounds__(256) k_scale(float4* __restrict__ e) {
    int i = blockIdx.x * 256 + threadIdx.x;
    float4 v = e[i];
    v.x *= 0.125f; v.y *= 0.125f; v.z *= 0.125f; v.w *= 0.125f;
    e[i] = v;
}

// ---------------- launch -----------------------------------------------------
extern "C" void kernel_launch(void* const* d_in, const int* in_sizes, int n_in,
                              void* d_out, int out_size) {
    const float* x   = (const float*)d_in[0];
    const float* Wq  = (const float*)d_in[1];
    const float* Wk  = (const float*)d_in[2];
    const float* Wvd = (const float*)d_in[3];
    const float* Wvu = (const float*)d_in[4];
    float* e = (float*)d_out;

    k_copy<<<NTOK * DEMB / 4 / 256, 256>>>((float4*)e, (const float4*)x);
    for (int h = 0; h < NH; h++) {
        k_gemm_qkv<<<dim3(2, 32, 3), 256>>>(e, Wq + (size_t)h * DH * DEMB,
                                            Wk + (size_t)h * DH * DEMB,
                                            Wvd + (size_t)h * DH * DEMB);
        k_attn<<<NTOK / 32, 256>>>();
        k_gemm_out<<<dim3(16, 32), 256>>>(Wvu + (size_t)h * DEMB * DH);
        k_norm<<<NTOK, 256>>>(e);
    }
    k_scale<<<NTOK * DEMB / 4 / 256, 256>>>((float4*)e);
}